// round 2
// baseline (speedup 1.0000x reference)
#include <cuda_runtime.h>
#include <math.h>

#define N_TOK 12288
#define DIMC  768
#define HEADS 12
#define HD    64
#define WSZ   64
#define NWIN  192
#define BATCH 2
#define M_ROWS (BATCH * N_TOK)   // 24576
#define SHIFT 32
#define SCALE 0.125f             // HD^-0.5

// ---------------- scratch (device globals; no cudaMalloc allowed) ----------
// g_big serves as qkv scratch (24576*2304 floats) during attention, then is
// reused as the MLP hidden buffer (24576*3072 floats) — lifetimes don't overlap.
__device__ float g_big[M_ROWS * 4 * DIMC];    // max(3*DIMC, 4*DIMC) per row
__device__ float g_hs [M_ROWS * DIMC];        // LN1(rolled x), later LN2(x2)
__device__ float g_o  [M_ROWS * DIMC];        // attention output (shifted space)
__device__ float g_x2 [M_ROWS * DIMC];        // x + rolled-back proj (residual 1)

// ---------------- fused LayerNorm (+ optional cyclic roll on source) -------
__global__ __launch_bounds__(256) void ln_kernel(
    const float* __restrict__ x, const float* __restrict__ g,
    const float* __restrict__ b, float* __restrict__ out, int rollOff)
{
    int r  = blockIdx.x;                 // output row 0..M_ROWS-1
    int bb = r / N_TOK;
    int n  = r - bb * N_TOK;
    int src = bb * N_TOK + (n + rollOff) % N_TOK;
    const float* xr = x + (size_t)src * DIMC;

    int c = threadIdx.x;
    float v0 = xr[c], v1 = xr[c + 256], v2 = xr[c + 512];
    float s  = v0 + v1 + v2;
    float ss = v0 * v0 + v1 * v1 + v2 * v2;
    #pragma unroll
    for (int o = 16; o > 0; o >>= 1) {
        s  += __shfl_xor_sync(0xFFFFFFFFu, s, o);
        ss += __shfl_xor_sync(0xFFFFFFFFu, ss, o);
    }
    __shared__ float sm[8], sm2[8], stat[2];
    int warp = threadIdx.x >> 5;
    if ((threadIdx.x & 31) == 0) { sm[warp] = s; sm2[warp] = ss; }
    __syncthreads();
    if (threadIdx.x == 0) {
        float ts = 0.f, tss = 0.f;
        #pragma unroll
        for (int i = 0; i < 8; i++) { ts += sm[i]; tss += sm2[i]; }
        float m   = ts * (1.f / 768.f);
        float var = tss * (1.f / 768.f) - m * m;
        stat[0] = m;
        stat[1] = rsqrtf(var + 1e-5f);
    }
    __syncthreads();
    float m = stat[0], inv = stat[1];
    float* orow = out + (size_t)r * DIMC;
    orow[c]       = (v0 - m) * inv * g[c]       + b[c];
    orow[c + 256] = (v1 - m) * inv * g[c + 256] + b[c + 256];
    orow[c + 512] = (v2 - m) * inv * g[c + 512] + b[c + 512];
}

// ---------------- SGEMM: C = A[M,K] @ B[Nn,K]^T + bias, fused epilogues ----
// EPI 0: bias            (qkv)
// EPI 1: bias + GELU     (fc1)
// EPI 2: bias + residual (fc2 -> d_out, res = x2)
// EPI 3: bias + roll(+SHIFT) row remap + residual (proj -> x2, res = x)
template <int EPI>
__global__ __launch_bounds__(256) void sgemm(
    const float* __restrict__ A, const float* __restrict__ B,
    const float* __restrict__ bias, const float* __restrict__ res,
    float* __restrict__ C, int M, int Nn, int K)
{
    __shared__ float As[8][128];
    __shared__ float Bs[8][128];

    int tid = threadIdx.x;
    int tx = tid & 15, ty = tid >> 4;

    float acc[8][8];
    #pragma unroll
    for (int i = 0; i < 8; i++)
        #pragma unroll
        for (int j = 0; j < 8; j++) acc[i][j] = 0.f;

    int lRow = tid >> 1;           // 0..127
    int lCol = (tid & 1) * 4;      // 0 or 4
    const float* Ap = A + (size_t)(blockIdx.y * 128 + lRow) * K + lCol;
    const float* Bp = B + (size_t)(blockIdx.x * 128 + lRow) * K + lCol;

    for (int kt = 0; kt < K; kt += 8) {
        float4 a4 = *(const float4*)(Ap + kt);
        float4 b4 = *(const float4*)(Bp + kt);
        As[lCol + 0][lRow] = a4.x; As[lCol + 1][lRow] = a4.y;
        As[lCol + 2][lRow] = a4.z; As[lCol + 3][lRow] = a4.w;
        Bs[lCol + 0][lRow] = b4.x; Bs[lCol + 1][lRow] = b4.y;
        Bs[lCol + 2][lRow] = b4.z; Bs[lCol + 3][lRow] = b4.w;
        __syncthreads();
        #pragma unroll
        for (int k = 0; k < 8; k++) {
            float af[8], bf[8];
            *(float4*)(af)     = *(const float4*)&As[k][ty * 8];
            *(float4*)(af + 4) = *(const float4*)&As[k][ty * 8 + 4];
            *(float4*)(bf)     = *(const float4*)&Bs[k][tx * 8];
            *(float4*)(bf + 4) = *(const float4*)&Bs[k][tx * 8 + 4];
            #pragma unroll
            for (int i = 0; i < 8; i++)
                #pragma unroll
                for (int j = 0; j < 8; j++)
                    acc[i][j] += af[i] * bf[j];
        }
        __syncthreads();
    }

    int col0 = blockIdx.x * 128 + tx * 8;
    float bv[8];
    #pragma unroll
    for (int j = 0; j < 8; j++) bv[j] = bias[col0 + j];

    #pragma unroll
    for (int i = 0; i < 8; i++) {
        int r = blockIdx.y * 128 + ty * 8 + i;
        int outr = r;
        if (EPI == 3) {
            int bb = r / N_TOK;
            int n  = r - bb * N_TOK;
            outr = bb * N_TOK + (n + SHIFT) % N_TOK;
        }
        float* crow = C + (size_t)outr * Nn + col0;
        const float* rrow = (EPI >= 2) ? (res + (size_t)outr * Nn + col0) : nullptr;
        #pragma unroll
        for (int j = 0; j < 8; j++) {
            float v = acc[i][j] + bv[j];
            if (EPI == 1) v = 0.5f * v * (1.f + erff(v * 0.70710678118f));
            if (EPI >= 2) v += rrow[j];
            crow[j] = v;
        }
    }
}

// ---------------- windowed attention: one block per (window, head) ---------
__global__ __launch_bounds__(256) void attn_kernel(
    const float* __restrict__ qkv, const float* __restrict__ table,
    float* __restrict__ out)
{
    __shared__ float qT[64 * 64];  // qT[d*64+i]; reused as attnT[j*64+i]
    __shared__ float kT[64 * 64];  // kT[d*64+j]
    __shared__ float vs[64 * 64];  // vs[j*64+d]

    int w = blockIdx.x, h = blockIdx.y;
    int tid = threadIdx.x;
    int i = tid >> 2;              // pixel/row 0..63
    int c = tid & 3;               // quarter 0..3
    int d0 = c * 16;

    const float* base = qkv + (size_t)(w * 64) * (3 * DIMC) + h * HD;
    {
        const float* qrow = base + (size_t)i * (3 * DIMC) + d0;
        const float* krow = qrow + DIMC;
        const float* vrow = qrow + 2 * DIMC;
        #pragma unroll
        for (int m = 0; m < 16; m += 4) {
            float4 q4 = *(const float4*)(qrow + m);
            qT[(d0 + m + 0) * 64 + i] = q4.x * SCALE;
            qT[(d0 + m + 1) * 64 + i] = q4.y * SCALE;
            qT[(d0 + m + 2) * 64 + i] = q4.z * SCALE;
            qT[(d0 + m + 3) * 64 + i] = q4.w * SCALE;
            float4 k4 = *(const float4*)(krow + m);
            kT[(d0 + m + 0) * 64 + i] = k4.x;
            kT[(d0 + m + 1) * 64 + i] = k4.y;
            kT[(d0 + m + 2) * 64 + i] = k4.z;
            kT[(d0 + m + 3) * 64 + i] = k4.w;
            float4 v4 = *(const float4*)(vrow + m);
            *(float4*)&vs[i * 64 + d0 + m] = v4;
        }
    }
    __syncthreads();

    // Q @ K^T for 16 columns j = c*16 .. c*16+15
    float dot[16];
    #pragma unroll
    for (int m = 0; m < 16; m++) dot[m] = 0.f;
    for (int d = 0; d < 64; d++) {
        float qv = qT[d * 64 + i];
        #pragma unroll
        for (int m = 0; m < 16; m += 4) {
            float4 k4 = *(const float4*)&kT[d * 64 + d0 + m];
            dot[m + 0] += qv * k4.x;
            dot[m + 1] += qv * k4.y;
            dot[m + 2] += qv * k4.z;
            dot[m + 3] += qv * k4.w;
        }
    }

    // relative-position bias (NEST/Morton de-interleave) + SW mask
    int ri = ((i >> 1) & 1) | (((i >> 3) & 1) << 1) | (((i >> 5) & 1) << 2);
    int ci = (i & 1)        | (((i >> 2) & 1) << 1) | (((i >> 4) & 1) << 2);
    bool maskwin = (w % NWIN) == (NWIN - 1);
    #pragma unroll
    for (int m = 0; m < 16; m++) {
        int j  = d0 + m;
        int rj = ((j >> 1) & 1) | (((j >> 3) & 1) << 1) | (((j >> 5) & 1) << 2);
        int cj = (j & 1)        | (((j >> 2) & 1) << 1) | (((j >> 4) & 1) << 2);
        int rpi = (ri - rj + 7) * 15 + (ci - cj + 7);
        dot[m] += table[rpi * HEADS + h];
        if (maskwin && ((i < 32) != (j < 32))) dot[m] -= 100.f;
    }

    // softmax over row i (16 local values x 4 threads in a lane-group)
    float mx = -1e30f;
    #pragma unroll
    for (int m = 0; m < 16; m++) mx = fmaxf(mx, dot[m]);
    mx = fmaxf(mx, __shfl_xor_sync(0xFFFFFFFFu, mx, 1));
    mx = fmaxf(mx, __shfl_xor_sync(0xFFFFFFFFu, mx, 2));
    float sum = 0.f;
    #pragma unroll
    for (int m = 0; m < 16; m++) { dot[m] = __expf(dot[m] - mx); sum += dot[m]; }
    sum += __shfl_xor_sync(0xFFFFFFFFu, sum, 1);
    sum += __shfl_xor_sync(0xFFFFFFFFu, sum, 2);
    float inv = 1.f / sum;

    __syncthreads();                       // everyone done reading qT
    #pragma unroll
    for (int m = 0; m < 16; m++) qT[(d0 + m) * 64 + i] = dot[m] * inv;  // attnT[j][i]
    __syncthreads();

    // P @ V : 16 output dims d = c*16 .. +15 for row i
    float o[16];
    #pragma unroll
    for (int m = 0; m < 16; m++) o[m] = 0.f;
    for (int j = 0; j < 64; j++) {
        float a = qT[j * 64 + i];
        #pragma unroll
        for (int m = 0; m < 16; m += 4) {
            float4 v4 = *(const float4*)&vs[j * 64 + d0 + m];
            o[m + 0] += a * v4.x;
            o[m + 1] += a * v4.y;
            o[m + 2] += a * v4.z;
            o[m + 3] += a * v4.w;
        }
    }
    float* orow = out + (size_t)(w * 64 + i) * DIMC + h * HD + d0;
    #pragma unroll
    for (int m = 0; m < 16; m += 4) {
        float4 v4 = make_float4(o[m], o[m + 1], o[m + 2], o[m + 3]);
        *(float4*)(orow + m) = v4;
    }
}

// ---------------- launch ---------------------------------------------------
extern "C" void kernel_launch(void* const* d_in, const int* in_sizes, int n_in,
                              void* d_out, int out_size)
{
    const float* x    = (const float*)d_in[0];
    const float* n1g  = (const float*)d_in[1];
    const float* n1b  = (const float*)d_in[2];
    const float* qkvw = (const float*)d_in[3];
    const float* qkvb = (const float*)d_in[4];
    const float* tab  = (const float*)d_in[5];
    const float* pw   = (const float*)d_in[6];
    const float* pb   = (const float*)d_in[7];
    const float* n2g  = (const float*)d_in[8];
    const float* n2b  = (const float*)d_in[9];
    const float* f1w  = (const float*)d_in[10];
    const float* f1b  = (const float*)d_in[11];
    const float* f2w  = (const float*)d_in[12];
    const float* f2b  = (const float*)d_in[13];
    float* out = (float*)d_out;

    float *big, *hs, *oB, *x2;
    cudaGetSymbolAddress((void**)&big, g_big);
    cudaGetSymbolAddress((void**)&hs,  g_hs);
    cudaGetSymbolAddress((void**)&oB,  g_o);
    cudaGetSymbolAddress((void**)&x2,  g_x2);
    float* qkvB = big;   // lives until attn_kernel is done
    float* mid  = big;   // reused for MLP hidden afterwards

    // 1. LN1 + roll(-32)
    ln_kernel<<<M_ROWS, 256>>>(x, n1g, n1b, hs, SHIFT);
    // 2. QKV projection  (24576 x 2304 x 768)
    sgemm<0><<<dim3(2304 / 128, M_ROWS / 128), 256>>>(hs, qkvw, qkvb, nullptr, qkvB,
                                                      M_ROWS, 3 * DIMC, DIMC);
    // 3. windowed attention
    attn_kernel<<<dim3(BATCH * NWIN, HEADS), 256>>>(qkvB, tab, oB);
    // 4. proj + roll(+32) + residual -> x2
    sgemm<3><<<dim3(DIMC / 128, M_ROWS / 128), 256>>>(oB, pw, pb, x, x2,
                                                      M_ROWS, DIMC, DIMC);
    // 5. LN2
    ln_kernel<<<M_ROWS, 256>>>(x2, n2g, n2b, hs, 0);
    // 6. fc1 + GELU   (24576 x 3072 x 768)
    sgemm<1><<<dim3(3072 / 128, M_ROWS / 128), 256>>>(hs, f1w, f1b, nullptr, mid,
                                                      M_ROWS, 4 * DIMC, DIMC);
    // 7. fc2 + residual -> out  (24576 x 768 x 3072)
    sgemm<2><<<dim3(DIMC / 128, M_ROWS / 128), 256>>>(mid, f2w, f2b, x2, out,
                                                      M_ROWS, DIMC, 4 * DIMC);
}

// round 3
// speedup vs baseline: 2.2653x; 2.2653x over previous
#include <cuda_runtime.h>
#include <math.h>
#include <stdint.h>

#define N_TOK 12288
#define DIMC  768
#define HEADS 12
#define HD    64
#define NWIN  192
#define BATCH 2
#define M_ROWS (BATCH * N_TOK)   // 24576
#define SHIFT 32
#define SCALE 0.125f             // HD^-0.5

// ---------------- scratch (device globals; no cudaMalloc allowed) ----------
__device__ float g_big[M_ROWS * 4 * DIMC];    // qkv scratch, later MLP hidden
__device__ float g_hs [M_ROWS * DIMC];        // LN1(rolled x), later LN2(x2)
__device__ float g_o  [M_ROWS * DIMC];        // attention output (shifted space)
__device__ float g_x2 [M_ROWS * DIMC];        // x + rolled-back proj

__device__ __forceinline__ uint32_t f2tf32(float x) {
    uint32_t u;
    asm("cvt.rna.tf32.f32 %0, %1;" : "=r"(u) : "f"(x));
    return u;
}

// ---------------- fused LayerNorm (+ optional cyclic roll on source) -------
__global__ __launch_bounds__(256) void ln_kernel(
    const float* __restrict__ x, const float* __restrict__ g,
    const float* __restrict__ b, float* __restrict__ out, int rollOff)
{
    int r  = blockIdx.x;
    int bb = r / N_TOK;
    int n  = r - bb * N_TOK;
    int src = bb * N_TOK + (n + rollOff) % N_TOK;
    const float* xr = x + (size_t)src * DIMC;

    int c = threadIdx.x;
    float v0 = xr[c], v1 = xr[c + 256], v2 = xr[c + 512];
    float s  = v0 + v1 + v2;
    float ss = v0 * v0 + v1 * v1 + v2 * v2;
    #pragma unroll
    for (int o = 16; o > 0; o >>= 1) {
        s  += __shfl_xor_sync(0xFFFFFFFFu, s, o);
        ss += __shfl_xor_sync(0xFFFFFFFFu, ss, o);
    }
    __shared__ float sm[8], sm2[8], stat[2];
    int warp = threadIdx.x >> 5;
    if ((threadIdx.x & 31) == 0) { sm[warp] = s; sm2[warp] = ss; }
    __syncthreads();
    if (threadIdx.x == 0) {
        float ts = 0.f, tss = 0.f;
        #pragma unroll
        for (int i = 0; i < 8; i++) { ts += sm[i]; tss += sm2[i]; }
        float m   = ts * (1.f / 768.f);
        float var = tss * (1.f / 768.f) - m * m;
        stat[0] = m;
        stat[1] = rsqrtf(var + 1e-5f);
    }
    __syncthreads();
    float m = stat[0], inv = stat[1];
    float* orow = out + (size_t)r * DIMC;
    orow[c]       = (v0 - m) * inv * g[c]       + b[c];
    orow[c + 256] = (v1 - m) * inv * g[c + 256] + b[c + 256];
    orow[c + 512] = (v2 - m) * inv * g[c + 512] + b[c + 512];
}

// ---------------- tf32 tensor-core GEMM: C = A[M,K] @ B[Nn,K]^T + bias -----
// EPI 0: bias            (qkv)
// EPI 1: bias + GELU     (fc1)
// EPI 2: bias + residual (fc2 -> d_out)
// EPI 3: bias + roll(+SHIFT) row remap + residual (proj -> x2)
//
// 128x128x32 tiles, 256 thr, warp grid 2(m) x 4(n), warp tile 64x32,
// 4x4 m16n8k8 fragments. Smem k-permuted: slot(k) = (k&3)*8 + (k>>2),
// row stride 34 -> fragment loads are conflict-free LDS.64.
#define SROW 34
template <int EPI>
__global__ __launch_bounds__(256, 2) void tgemm(
    const float* __restrict__ A, const float* __restrict__ B,
    const float* __restrict__ bias, const float* __restrict__ res,
    float* __restrict__ C, int M, int Nn, int K)
{
    __shared__ float As[128 * SROW];
    __shared__ float Bs[128 * SROW];

    const int tid  = threadIdx.x;
    const int lane = tid & 31;
    const int wid  = tid >> 5;
    const int wm   = wid >> 2;      // 0..1
    const int wn   = wid & 3;       // 0..3
    const int g    = lane >> 2;     // 0..7
    const int q    = lane & 3;      // 0..3

    const int rowA0 = blockIdx.y * 128;
    const int rowB0 = blockIdx.x * 128;

    float acc[4][4][4];
    #pragma unroll
    for (int a = 0; a < 4; a++)
        #pragma unroll
        for (int b = 0; b < 4; b++)
            #pragma unroll
            for (int e = 0; e < 4; e++) acc[a][b][e] = 0.f;

    // per-thread global-load coords: f = tid + it*256; m=f>>3; kq4=f&7
    float4 pa[4], pb[4];
    #pragma unroll
    for (int it = 0; it < 4; it++) {
        int f = tid + it * 256;
        int m = f >> 3, kq = (f & 7) << 2;
        pa[it] = *(const float4*)(A + (size_t)(rowA0 + m) * K + kq);
        pb[it] = *(const float4*)(B + (size_t)(rowB0 + m) * K + kq);
    }

    for (int kt = 0; kt < K; kt += 32) {
        // store prefetched tile (tf32-converted) into permuted smem
        #pragma unroll
        for (int it = 0; it < 4; it++) {
            int f = tid + it * 256;
            int m = f >> 3, kq4 = f & 7;
            float* ar = As + m * SROW + kq4;
            ar[0]  = __uint_as_float(f2tf32(pa[it].x));
            ar[8]  = __uint_as_float(f2tf32(pa[it].y));
            ar[16] = __uint_as_float(f2tf32(pa[it].z));
            ar[24] = __uint_as_float(f2tf32(pa[it].w));
            float* br = Bs + m * SROW + kq4;
            br[0]  = __uint_as_float(f2tf32(pb[it].x));
            br[8]  = __uint_as_float(f2tf32(pb[it].y));
            br[16] = __uint_as_float(f2tf32(pb[it].z));
            br[24] = __uint_as_float(f2tf32(pb[it].w));
        }
        __syncthreads();

        if (kt + 32 < K) {
            #pragma unroll
            for (int it = 0; it < 4; it++) {
                int f = tid + it * 256;
                int m = f >> 3, kq = (f & 7) << 2;
                pa[it] = *(const float4*)(A + (size_t)(rowA0 + m) * K + kt + 32 + kq);
                pb[it] = *(const float4*)(B + (size_t)(rowB0 + m) * K + kt + 32 + kq);
            }
        }

        #pragma unroll
        for (int j = 0; j < 4; j++) {
            uint32_t af[4][4];
            #pragma unroll
            for (int mf = 0; mf < 4; mf++) {
                int r0 = wm * 64 + mf * 16 + g;
                float2 lo = *(const float2*)&As[r0 * SROW + q * 8 + 2 * j];
                float2 hi = *(const float2*)&As[(r0 + 8) * SROW + q * 8 + 2 * j];
                af[mf][0] = __float_as_uint(lo.x);
                af[mf][1] = __float_as_uint(hi.x);
                af[mf][2] = __float_as_uint(lo.y);
                af[mf][3] = __float_as_uint(hi.y);
            }
            #pragma unroll
            for (int nf = 0; nf < 4; nf++) {
                int n0 = wn * 32 + nf * 8 + g;
                float2 bb = *(const float2*)&Bs[n0 * SROW + q * 8 + 2 * j];
                uint32_t b0 = __float_as_uint(bb.x);
                uint32_t b1 = __float_as_uint(bb.y);
                #pragma unroll
                for (int mf = 0; mf < 4; mf++) {
                    asm volatile(
                        "mma.sync.aligned.m16n8k8.row.col.f32.tf32.tf32.f32 "
                        "{%0,%1,%2,%3}, {%4,%5,%6,%7}, {%8,%9}, {%0,%1,%2,%3};\n"
                        : "+f"(acc[mf][nf][0]), "+f"(acc[mf][nf][1]),
                          "+f"(acc[mf][nf][2]), "+f"(acc[mf][nf][3])
                        : "r"(af[mf][0]), "r"(af[mf][1]),
                          "r"(af[mf][2]), "r"(af[mf][3]),
                          "r"(b0), "r"(b1));
                }
            }
        }
        __syncthreads();
    }

    // ---------------- epilogue ----------------
    const int r_base = blockIdx.y * 128 + wm * 64;
    const int c_base = blockIdx.x * 128 + wn * 32;
    #pragma unroll
    for (int mf = 0; mf < 4; mf++) {
        #pragma unroll
        for (int rr = 0; rr < 2; rr++) {
            int r = r_base + mf * 16 + g + rr * 8;
            int outr = r;
            if (EPI == 3) {
                int bb = r / N_TOK;
                int n  = r - bb * N_TOK;
                outr = bb * N_TOK + (n + SHIFT) % N_TOK;
            }
            float* crow = C + (size_t)outr * Nn;
            const float* rrow = (EPI >= 2) ? (res + (size_t)outr * Nn) : nullptr;
            #pragma unroll
            for (int nf = 0; nf < 4; nf++) {
                int c = c_base + nf * 8 + q * 2;
                float2 bv = *(const float2*)&bias[c];
                float v0 = acc[mf][nf][rr * 2 + 0] + bv.x;
                float v1 = acc[mf][nf][rr * 2 + 1] + bv.y;
                if (EPI == 1) {
                    v0 = 0.5f * v0 * (1.f + erff(v0 * 0.70710678118f));
                    v1 = 0.5f * v1 * (1.f + erff(v1 * 0.70710678118f));
                }
                if (EPI >= 2) {
                    float2 rv = *(const float2*)&rrow[c];
                    v0 += rv.x; v1 += rv.y;
                }
                *(float2*)&crow[c] = make_float2(v0, v1);
            }
        }
    }
}

// ---------------- windowed attention: one block per (window, head) ---------
__global__ __launch_bounds__(256) void attn_kernel(
    const float* __restrict__ qkv, const float* __restrict__ table,
    float* __restrict__ out)
{
    __shared__ float qT[64 * 64];
    __shared__ float kT[64 * 64];
    __shared__ float vs[64 * 64];

    int w = blockIdx.x, h = blockIdx.y;
    int tid = threadIdx.x;
    int i = tid >> 2;
    int c = tid & 3;
    int d0 = c * 16;

    const float* base = qkv + (size_t)(w * 64) * (3 * DIMC) + h * HD;
    {
        const float* qrow = base + (size_t)i * (3 * DIMC) + d0;
        const float* krow = qrow + DIMC;
        const float* vrow = qrow + 2 * DIMC;
        #pragma unroll
        for (int m = 0; m < 16; m += 4) {
            float4 q4 = *(const float4*)(qrow + m);
            qT[(d0 + m + 0) * 64 + i] = q4.x * SCALE;
            qT[(d0 + m + 1) * 64 + i] = q4.y * SCALE;
            qT[(d0 + m + 2) * 64 + i] = q4.z * SCALE;
            qT[(d0 + m + 3) * 64 + i] = q4.w * SCALE;
            float4 k4 = *(const float4*)(krow + m);
            kT[(d0 + m + 0) * 64 + i] = k4.x;
            kT[(d0 + m + 1) * 64 + i] = k4.y;
            kT[(d0 + m + 2) * 64 + i] = k4.z;
            kT[(d0 + m + 3) * 64 + i] = k4.w;
            float4 v4 = *(const float4*)(vrow + m);
            *(float4*)&vs[i * 64 + d0 + m] = v4;
        }
    }
    __syncthreads();

    float dot[16];
    #pragma unroll
    for (int m = 0; m < 16; m++) dot[m] = 0.f;
    for (int d = 0; d < 64; d++) {
        float qv = qT[d * 64 + i];
        #pragma unroll
        for (int m = 0; m < 16; m += 4) {
            float4 k4 = *(const float4*)&kT[d * 64 + d0 + m];
            dot[m + 0] += qv * k4.x;
            dot[m + 1] += qv * k4.y;
            dot[m + 2] += qv * k4.z;
            dot[m + 3] += qv * k4.w;
        }
    }

    int ri = ((i >> 1) & 1) | (((i >> 3) & 1) << 1) | (((i >> 5) & 1) << 2);
    int ci = (i & 1)        | (((i >> 2) & 1) << 1) | (((i >> 4) & 1) << 2);
    bool maskwin = (w % NWIN) == (NWIN - 1);
    #pragma unroll
    for (int m = 0; m < 16; m++) {
        int j  = d0 + m;
        int rj = ((j >> 1) & 1) | (((j >> 3) & 1) << 1) | (((j >> 5) & 1) << 2);
        int cj = (j & 1)        | (((j >> 2) & 1) << 1) | (((j >> 4) & 1) << 2);
        int rpi = (ri - rj + 7) * 15 + (ci - cj + 7);
        dot[m] += table[rpi * HEADS + h];
        if (maskwin && ((i < 32) != (j < 32))) dot[m] -= 100.f;
    }

    float mx = -1e30f;
    #pragma unroll
    for (int m = 0; m < 16; m++) mx = fmaxf(mx, dot[m]);
    mx = fmaxf(mx, __shfl_xor_sync(0xFFFFFFFFu, mx, 1));
    mx = fmaxf(mx, __shfl_xor_sync(0xFFFFFFFFu, mx, 2));
    float sum = 0.f;
    #pragma unroll
    for (int m = 0; m < 16; m++) { dot[m] = __expf(dot[m] - mx); sum += dot[m]; }
    sum += __shfl_xor_sync(0xFFFFFFFFu, sum, 1);
    sum += __shfl_xor_sync(0xFFFFFFFFu, sum, 2);
    float inv = 1.f / sum;

    __syncthreads();
    #pragma unroll
    for (int m = 0; m < 16; m++) qT[(d0 + m) * 64 + i] = dot[m] * inv;
    __syncthreads();

    float o[16];
    #pragma unroll
    for (int m = 0; m < 16; m++) o[m] = 0.f;
    for (int j = 0; j < 64; j++) {
        float a = qT[j * 64 + i];
        #pragma unroll
        for (int m = 0; m < 16; m += 4) {
            float4 v4 = *(const float4*)&vs[j * 64 + d0 + m];
            o[m + 0] += a * v4.x;
            o[m + 1] += a * v4.y;
            o[m + 2] += a * v4.z;
            o[m + 3] += a * v4.w;
        }
    }
    float* orow = out + (size_t)(w * 64 + i) * DIMC + h * HD + d0;
    #pragma unroll
    for (int m = 0; m < 16; m += 4) {
        *(float4*)(orow + m) = make_float4(o[m], o[m + 1], o[m + 2], o[m + 3]);
    }
}

// ---------------- launch ---------------------------------------------------
extern "C" void kernel_launch(void* const* d_in, const int* in_sizes, int n_in,
                              void* d_out, int out_size)
{
    const float* x    = (const float*)d_in[0];
    const float* n1g  = (const float*)d_in[1];
    const float* n1b  = (const float*)d_in[2];
    const float* qkvw = (const float*)d_in[3];
    const float* qkvb = (const float*)d_in[4];
    const float* tab  = (const float*)d_in[5];
    const float* pw   = (const float*)d_in[6];
    const float* pb   = (const float*)d_in[7];
    const float* n2g  = (const float*)d_in[8];
    const float* n2b  = (const float*)d_in[9];
    const float* f1w  = (const float*)d_in[10];
    const float* f1b  = (const float*)d_in[11];
    const float* f2w  = (const float*)d_in[12];
    const float* f2b  = (const float*)d_in[13];
    float* out = (float*)d_out;

    float *big, *hs, *oB, *x2;
    cudaGetSymbolAddress((void**)&big, g_big);
    cudaGetSymbolAddress((void**)&hs,  g_hs);
    cudaGetSymbolAddress((void**)&oB,  g_o);
    cudaGetSymbolAddress((void**)&x2,  g_x2);
    float* qkvB = big;
    float* mid  = big;

    // 1. LN1 + roll(-32)
    ln_kernel<<<M_ROWS, 256>>>(x, n1g, n1b, hs, SHIFT);
    // 2. QKV projection  (24576 x 2304 x 768)
    tgemm<0><<<dim3(2304 / 128, M_ROWS / 128), 256>>>(hs, qkvw, qkvb, nullptr, qkvB,
                                                      M_ROWS, 3 * DIMC, DIMC);
    // 3. windowed attention
    attn_kernel<<<dim3(BATCH * NWIN, HEADS), 256>>>(qkvB, tab, oB);
    // 4. proj + roll(+32) + residual -> x2
    tgemm<3><<<dim3(DIMC / 128, M_ROWS / 128), 256>>>(oB, pw, pb, x, x2,
                                                      M_ROWS, DIMC, DIMC);
    // 5. LN2
    ln_kernel<<<M_ROWS, 256>>>(x2, n2g, n2b, hs, 0);
    // 6. fc1 + GELU   (24576 x 3072 x 768)
    tgemm<1><<<dim3(3072 / 128, M_ROWS / 128), 256>>>(hs, f1w, f1b, nullptr, mid,
                                                      M_ROWS, 4 * DIMC, DIMC);
    // 7. fc2 + residual -> out  (24576 x 768 x 3072)
    tgemm<2><<<dim3(DIMC / 128, M_ROWS / 128), 256>>>(mid, f2w, f2b, x2, out,
                                                      M_ROWS, DIMC, 4 * DIMC);
}

// round 4
// speedup vs baseline: 3.7616x; 1.6605x over previous
#include <cuda_runtime.h>
#include <math.h>
#include <stdint.h>

#define N_TOK 12288
#define DIMC  768
#define HEADS 12
#define HD    64
#define NWIN  192
#define BATCH 2
#define M_ROWS (BATCH * N_TOK)   // 24576
#define SHIFT 32
#define SCALE 0.125f

// ---------------- scratch (device globals) ---------------------------------
__device__ float g_big[M_ROWS * 4 * DIMC];    // qkv scratch, later MLP hidden
__device__ float g_hs [M_ROWS * DIMC];        // LN outputs (tf32-rounded)
__device__ float g_o  [M_ROWS * DIMC];        // attention out (tf32-rounded)
__device__ float g_x2 [M_ROWS * DIMC];        // x + proj residual (fp32)
// tf32-rounded weights: qkv | proj | fc1 | fc2
#define W_QKV 0
#define W_PROJ (W_QKV + 3 * DIMC * DIMC)
#define W_FC1  (W_PROJ + DIMC * DIMC)
#define W_FC2  (W_FC1 + 4 * DIMC * DIMC)
#define W_TOT  (W_FC2 + 4 * DIMC * DIMC)
__device__ float g_wt[W_TOT];

__device__ __forceinline__ float tf32r(float x) {
    uint32_t u;
    asm("cvt.rna.tf32.f32 %0, %1;" : "=r"(u) : "f"(x));
    return __uint_as_float(u);
}

// ---------------- weight tf32 pre-round ------------------------------------
__global__ __launch_bounds__(256) void cvt_kernel(
    const float4* __restrict__ in, float4* __restrict__ out, int n4)
{
    int i = blockIdx.x * 256 + threadIdx.x;
    if (i < n4) {
        float4 v = in[i];
        v.x = tf32r(v.x); v.y = tf32r(v.y); v.z = tf32r(v.z); v.w = tf32r(v.w);
        out[i] = v;
    }
}

// ---------------- fused LayerNorm (+ roll), tf32-rounded output ------------
__global__ __launch_bounds__(256) void ln_kernel(
    const float* __restrict__ x, const float* __restrict__ g,
    const float* __restrict__ b, float* __restrict__ out, int rollOff)
{
    int r  = blockIdx.x;
    int bb = r / N_TOK;
    int n  = r - bb * N_TOK;
    int src = bb * N_TOK + (n + rollOff) % N_TOK;
    const float* xr = x + (size_t)src * DIMC;

    int c = threadIdx.x;
    float v0 = xr[c], v1 = xr[c + 256], v2 = xr[c + 512];
    float s  = v0 + v1 + v2;
    float ss = v0 * v0 + v1 * v1 + v2 * v2;
    #pragma unroll
    for (int o = 16; o > 0; o >>= 1) {
        s  += __shfl_xor_sync(0xFFFFFFFFu, s, o);
        ss += __shfl_xor_sync(0xFFFFFFFFu, ss, o);
    }
    __shared__ float sm[8], sm2[8], stat[2];
    int warp = threadIdx.x >> 5;
    if ((threadIdx.x & 31) == 0) { sm[warp] = s; sm2[warp] = ss; }
    __syncthreads();
    if (threadIdx.x == 0) {
        float ts = 0.f, tss = 0.f;
        #pragma unroll
        for (int i = 0; i < 8; i++) { ts += sm[i]; tss += sm2[i]; }
        float m   = ts * (1.f / 768.f);
        float var = tss * (1.f / 768.f) - m * m;
        stat[0] = m;
        stat[1] = rsqrtf(var + 1e-5f);
    }
    __syncthreads();
    float m = stat[0], inv = stat[1];
    float* orow = out + (size_t)r * DIMC;
    orow[c]       = tf32r((v0 - m) * inv * g[c]       + b[c]);
    orow[c + 256] = tf32r((v1 - m) * inv * g[c + 256] + b[c + 256]);
    orow[c + 512] = tf32r((v2 - m) * inv * g[c + 512] + b[c + 512]);
}

// ---------------- tf32 tensor-core GEMM (cp.async + ldmatrix) --------------
// C = A[M,K] @ B[Nn,K]^T + bias.  A, B already tf32-rounded.
// EPI 0: bias (round out)    1: bias+GELU (round out)
// EPI 2: bias+residual       3: bias + roll(+SHIFT) remap + residual
// 128x128x32 tile, 256 thr, warps 2(m) x 4(n), warp tile 64x32.
// SMEM: row-major 128B rows, 16B chunk swizzle: phys = chunk ^ (row&7).
#define KT 32
#define STAGE_BYTES 32768
#define NSTAGE 3

__device__ __forceinline__ void cp16(uint32_t dst, const void* src) {
    asm volatile("cp.async.cg.shared.global [%0], [%1], 16;\n" :: "r"(dst), "l"(src));
}
__device__ __forceinline__ void ldsm4(uint32_t& r0, uint32_t& r1,
                                      uint32_t& r2, uint32_t& r3, uint32_t a) {
    asm volatile("ldmatrix.sync.aligned.m8n8.x4.shared.b16 {%0,%1,%2,%3}, [%4];\n"
                 : "=r"(r0), "=r"(r1), "=r"(r2), "=r"(r3) : "r"(a));
}

template <int EPI>
__global__ __launch_bounds__(256, 2) void tgemm(
    const float* __restrict__ A, const float* __restrict__ B,
    const float* __restrict__ bias, const float* __restrict__ res,
    float* __restrict__ C, int M, int Nn, int K)
{
    extern __shared__ float smem[];
    uint32_t sbase = (uint32_t)__cvta_generic_to_shared(smem);

    const int tid  = threadIdx.x;
    const int lane = tid & 31;
    const int wid  = tid >> 5;
    const int wm   = wid >> 2;
    const int wn   = wid & 3;
    const int g    = lane >> 2;
    const int q    = lane & 3;

    const int rowA0 = blockIdx.y * 128;
    const int rowB0 = blockIdx.x * 128;

    // ---- cp.async coords: thread covers rows (tid>>3)+32r, 16B chunk tid&7
    const int ldr   = tid >> 3;          // 0..31
    const int lc    = tid & 7;           // logical chunk
    const uint32_t pcoff = (uint32_t)((lc ^ (ldr & 7)) << 4);
    const uint32_t rowOff = (uint32_t)(ldr << 7);   // *128 B
    const float* gA = A + (size_t)(rowA0 + ldr) * K + lc * 4;
    const float* gB = B + (size_t)(rowB0 + ldr) * K + lc * 4;

    // ---- ldmatrix per-lane address bases
    const int t8 = lane >> 3;            // matrix group 0..3
    const int thA = t8 >> 1;             // k-chunk select for A
    const int tlA = t8 & 1;              // row-half select for A
    uint32_t aBaseOff[4]; int aRx[4];
    #pragma unroll
    for (int mf = 0; mf < 4; mf++) {
        int r = wm * 64 + mf * 16 + tlA * 8 + (lane & 7);
        aBaseOff[mf] = (uint32_t)(r << 7);
        aRx[mf] = r & 7;
    }
    const int tbB = t8 & 1;              // k-chunk select for B
    uint32_t bBaseOff[2]; int bRx[2];
    #pragma unroll
    for (int p = 0; p < 2; p++) {
        int n = wn * 32 + (p * 2 + (t8 >> 1)) * 8 + (lane & 7);
        bBaseOff[p] = (uint32_t)(n << 7);
        bRx[p] = n & 7;
    }

    float acc[4][4][4];
    #pragma unroll
    for (int a = 0; a < 4; a++)
        #pragma unroll
        for (int b = 0; b < 4; b++)
            #pragma unroll
            for (int e = 0; e < 4; e++) acc[a][b][e] = 0.f;

    const int nk = K / KT;

    auto issue = [&](int stage, int kt) {
        uint32_t sa = sbase + stage * STAGE_BYTES + rowOff + pcoff;
        uint32_t sb = sa + 16384u;
        const float* pa = gA + kt * KT;
        const float* pb = gB + kt * KT;
        #pragma unroll
        for (int r = 0; r < 4; r++) {
            cp16(sa + r * (32u << 7), pa + (size_t)r * 32 * K);
            cp16(sb + r * (32u << 7), pb + (size_t)r * 32 * K);
        }
        asm volatile("cp.async.commit_group;\n");
    };

    issue(0, 0);
    issue(1, 1);

    for (int kt = 0; kt < nk; kt++) {
        asm volatile("cp.async.wait_group 1;\n");
        __syncthreads();
        if (kt + 2 < nk) issue((kt + 2) % NSTAGE, kt + 2);
        else asm volatile("cp.async.commit_group;\n");

        uint32_t aS = sbase + (kt % NSTAGE) * STAGE_BYTES;
        uint32_t bS = aS + 16384u;

        #pragma unroll
        for (int j = 0; j < 4; j++) {
            uint32_t af[4][4];
            #pragma unroll
            for (int mf = 0; mf < 4; mf++)
                ldsm4(af[mf][0], af[mf][1], af[mf][2], af[mf][3],
                      aS + aBaseOff[mf] + (uint32_t)(((2 * j + thA) ^ aRx[mf]) << 4));
            uint32_t bf[2][4];
            #pragma unroll
            for (int p = 0; p < 2; p++)
                ldsm4(bf[p][0], bf[p][1], bf[p][2], bf[p][3],
                      bS + bBaseOff[p] + (uint32_t)(((2 * j + tbB) ^ bRx[p]) << 4));
            #pragma unroll
            for (int nf = 0; nf < 4; nf++) {
                uint32_t b0 = bf[nf >> 1][(nf & 1) * 2];
                uint32_t b1 = bf[nf >> 1][(nf & 1) * 2 + 1];
                #pragma unroll
                for (int mf = 0; mf < 4; mf++) {
                    asm volatile(
                        "mma.sync.aligned.m16n8k8.row.col.f32.tf32.tf32.f32 "
                        "{%0,%1,%2,%3}, {%4,%5,%6,%7}, {%8,%9}, {%0,%1,%2,%3};\n"
                        : "+f"(acc[mf][nf][0]), "+f"(acc[mf][nf][1]),
                          "+f"(acc[mf][nf][2]), "+f"(acc[mf][nf][3])
                        : "r"(af[mf][0]), "r"(af[mf][1]),
                          "r"(af[mf][2]), "r"(af[mf][3]),
                          "r"(b0), "r"(b1));
                }
            }
        }
        __syncthreads();
    }

    // ---------------- epilogue ----------------
    const int r_base = blockIdx.y * 128 + wm * 64;
    const int c_base = blockIdx.x * 128 + wn * 32;
    #pragma unroll
    for (int mf = 0; mf < 4; mf++) {
        #pragma unroll
        for (int rr = 0; rr < 2; rr++) {
            int r = r_base + mf * 16 + g + rr * 8;
            int outr = r;
            if (EPI == 3) {
                int bb = r / N_TOK;
                int n  = r - bb * N_TOK;
                outr = bb * N_TOK + (n + SHIFT) % N_TOK;
            }
            float* crow = C + (size_t)outr * Nn;
            const float* rrow = (EPI >= 2) ? (res + (size_t)outr * Nn) : nullptr;
            #pragma unroll
            for (int nf = 0; nf < 4; nf++) {
                int c = c_base + nf * 8 + q * 2;
                float2 bv = *(const float2*)&bias[c];
                float v0 = acc[mf][nf][rr * 2 + 0] + bv.x;
                float v1 = acc[mf][nf][rr * 2 + 1] + bv.y;
                if (EPI == 1) {
                    v0 = 0.5f * v0 * (1.f + erff(v0 * 0.70710678118f));
                    v1 = 0.5f * v1 * (1.f + erff(v1 * 0.70710678118f));
                }
                if (EPI >= 2) {
                    float2 rv = *(const float2*)&rrow[c];
                    v0 += rv.x; v1 += rv.y;
                } else {
                    v0 = tf32r(v0); v1 = tf32r(v1);   // outputs feed next GEMM
                }
                *(float2*)&crow[c] = make_float2(v0, v1);
            }
        }
    }
}

// ---------------- windowed attention ---------------------------------------
__global__ __launch_bounds__(256) void attn_kernel(
    const float* __restrict__ qkv, const float* __restrict__ table,
    float* __restrict__ out)
{
    __shared__ float qT[64 * 64];
    __shared__ float kT[64 * 64];
    __shared__ float vs[64 * 64];

    int w = blockIdx.x, h = blockIdx.y;
    int tid = threadIdx.x;
    int i = tid >> 2;
    int c = tid & 3;
    int d0 = c * 16;

    const float* base = qkv + (size_t)(w * 64) * (3 * DIMC) + h * HD;
    {
        const float* qrow = base + (size_t)i * (3 * DIMC) + d0;
        const float* krow = qrow + DIMC;
        const float* vrow = qrow + 2 * DIMC;
        #pragma unroll
        for (int m = 0; m < 16; m += 4) {
            float4 q4 = *(const float4*)(qrow + m);
            qT[(d0 + m + 0) * 64 + i] = q4.x * SCALE;
            qT[(d0 + m + 1) * 64 + i] = q4.y * SCALE;
            qT[(d0 + m + 2) * 64 + i] = q4.z * SCALE;
            qT[(d0 + m + 3) * 64 + i] = q4.w * SCALE;
            float4 k4 = *(const float4*)(krow + m);
            kT[(d0 + m + 0) * 64 + i] = k4.x;
            kT[(d0 + m + 1) * 64 + i] = k4.y;
            kT[(d0 + m + 2) * 64 + i] = k4.z;
            kT[(d0 + m + 3) * 64 + i] = k4.w;
            float4 v4 = *(const float4*)(vrow + m);
            *(float4*)&vs[i * 64 + d0 + m] = v4;
        }
    }
    __syncthreads();

    float dot[16];
    #pragma unroll
    for (int m = 0; m < 16; m++) dot[m] = 0.f;
    for (int d = 0; d < 64; d++) {
        float qv = qT[d * 64 + i];
        #pragma unroll
        for (int m = 0; m < 16; m += 4) {
            float4 k4 = *(const float4*)&kT[d * 64 + d0 + m];
            dot[m + 0] += qv * k4.x;
            dot[m + 1] += qv * k4.y;
            dot[m + 2] += qv * k4.z;
            dot[m + 3] += qv * k4.w;
        }
    }

    int ri = ((i >> 1) & 1) | (((i >> 3) & 1) << 1) | (((i >> 5) & 1) << 2);
    int ci = (i & 1)        | (((i >> 2) & 1) << 1) | (((i >> 4) & 1) << 2);
    bool maskwin = (w % NWIN) == (NWIN - 1);
    #pragma unroll
    for (int m = 0; m < 16; m++) {
        int j  = d0 + m;
        int rj = ((j >> 1) & 1) | (((j >> 3) & 1) << 1) | (((j >> 5) & 1) << 2);
        int cj = (j & 1)        | (((j >> 2) & 1) << 1) | (((j >> 4) & 1) << 2);
        int rpi = (ri - rj + 7) * 15 + (ci - cj + 7);
        dot[m] += table[rpi * HEADS + h];
        if (maskwin && ((i < 32) != (j < 32))) dot[m] -= 100.f;
    }

    float mx = -1e30f;
    #pragma unroll
    for (int m = 0; m < 16; m++) mx = fmaxf(mx, dot[m]);
    mx = fmaxf(mx, __shfl_xor_sync(0xFFFFFFFFu, mx, 1));
    mx = fmaxf(mx, __shfl_xor_sync(0xFFFFFFFFu, mx, 2));
    float sum = 0.f;
    #pragma unroll
    for (int m = 0; m < 16; m++) { dot[m] = __expf(dot[m] - mx); sum += dot[m]; }
    sum += __shfl_xor_sync(0xFFFFFFFFu, sum, 1);
    sum += __shfl_xor_sync(0xFFFFFFFFu, sum, 2);
    float inv = 1.f / sum;

    __syncthreads();
    #pragma unroll
    for (int m = 0; m < 16; m++) qT[(d0 + m) * 64 + i] = dot[m] * inv;
    __syncthreads();

    float o[16];
    #pragma unroll
    for (int m = 0; m < 16; m++) o[m] = 0.f;
    for (int j = 0; j < 64; j++) {
        float a = qT[j * 64 + i];
        #pragma unroll
        for (int m = 0; m < 16; m += 4) {
            float4 v4 = *(const float4*)&vs[j * 64 + d0 + m];
            o[m + 0] += a * v4.x;
            o[m + 1] += a * v4.y;
            o[m + 2] += a * v4.z;
            o[m + 3] += a * v4.w;
        }
    }
    float* orow = out + (size_t)(w * 64 + i) * DIMC + h * HD + d0;
    #pragma unroll
    for (int m = 0; m < 16; m += 4) {
        *(float4*)(orow + m) = make_float4(tf32r(o[m]), tf32r(o[m + 1]),
                                           tf32r(o[m + 2]), tf32r(o[m + 3]));
    }
}

// ---------------- launch ---------------------------------------------------
#define SMEM_GEMM (NSTAGE * STAGE_BYTES)

extern "C" void kernel_launch(void* const* d_in, const int* in_sizes, int n_in,
                              void* d_out, int out_size)
{
    const float* x    = (const float*)d_in[0];
    const float* n1g  = (const float*)d_in[1];
    const float* n1b  = (const float*)d_in[2];
    const float* qkvw = (const float*)d_in[3];
    const float* qkvb = (const float*)d_in[4];
    const float* tab  = (const float*)d_in[5];
    const float* pw   = (const float*)d_in[6];
    const float* pb   = (const float*)d_in[7];
    const float* n2g  = (const float*)d_in[8];
    const float* n2b  = (const float*)d_in[9];
    const float* f1w  = (const float*)d_in[10];
    const float* f1b  = (const float*)d_in[11];
    const float* f2w  = (const float*)d_in[12];
    const float* f2b  = (const float*)d_in[13];
    float* out = (float*)d_out;

    float *big, *hs, *oB, *x2, *wt;
    cudaGetSymbolAddress((void**)&big, g_big);
    cudaGetSymbolAddress((void**)&hs,  g_hs);
    cudaGetSymbolAddress((void**)&oB,  g_o);
    cudaGetSymbolAddress((void**)&x2,  g_x2);
    cudaGetSymbolAddress((void**)&wt,  g_wt);
    float* qkvB = big;
    float* mid  = big;

    static int smem_set = 0;
    if (!smem_set) {
        cudaFuncSetAttribute(tgemm<0>, cudaFuncAttributeMaxDynamicSharedMemorySize, SMEM_GEMM);
        cudaFuncSetAttribute(tgemm<1>, cudaFuncAttributeMaxDynamicSharedMemorySize, SMEM_GEMM);
        cudaFuncSetAttribute(tgemm<2>, cudaFuncAttributeMaxDynamicSharedMemorySize, SMEM_GEMM);
        cudaFuncSetAttribute(tgemm<3>, cudaFuncAttributeMaxDynamicSharedMemorySize, SMEM_GEMM);
        smem_set = 1;
    }

    // weight tf32 pre-round
    {
        int n;
        n = 3 * DIMC * DIMC / 4;
        cvt_kernel<<<(n + 255) / 256, 256>>>((const float4*)qkvw, (float4*)(wt + W_QKV), n);
        n = DIMC * DIMC / 4;
        cvt_kernel<<<(n + 255) / 256, 256>>>((const float4*)pw,   (float4*)(wt + W_PROJ), n);
        n = 4 * DIMC * DIMC / 4;
        cvt_kernel<<<(n + 255) / 256, 256>>>((const float4*)f1w,  (float4*)(wt + W_FC1), n);
        n = 4 * DIMC * DIMC / 4;
        cvt_kernel<<<(n + 255) / 256, 256>>>((const float4*)f2w,  (float4*)(wt + W_FC2), n);
    }

    // 1. LN1 + roll(-32)
    ln_kernel<<<M_ROWS, 256>>>(x, n1g, n1b, hs, SHIFT);
    // 2. QKV projection
    tgemm<0><<<dim3(2304 / 128, M_ROWS / 128), 256, SMEM_GEMM>>>(
        hs, wt + W_QKV, qkvb, nullptr, qkvB, M_ROWS, 3 * DIMC, DIMC);
    // 3. windowed attention
    attn_kernel<<<dim3(BATCH * NWIN, HEADS), 256>>>(qkvB, tab, oB);
    // 4. proj + roll(+32) + residual -> x2
    tgemm<3><<<dim3(DIMC / 128, M_ROWS / 128), 256, SMEM_GEMM>>>(
        oB, wt + W_PROJ, pb, x, x2, M_ROWS, DIMC, DIMC);
    // 5. LN2
    ln_kernel<<<M_ROWS, 256>>>(x2, n2g, n2b, hs, 0);
    // 6. fc1 + GELU
    tgemm<1><<<dim3(3072 / 128, M_ROWS / 128), 256, SMEM_GEMM>>>(
        hs, wt + W_FC1, f1b, nullptr, mid, M_ROWS, 4 * DIMC, DIMC);
    // 7. fc2 + residual -> out
    tgemm<2><<<dim3(DIMC / 128, M_ROWS / 128), 256, SMEM_GEMM>>>(
        mid, wt + W_FC2, f2b, x2, out, M_ROWS, DIMC, 4 * DIMC);
}

// round 6
// speedup vs baseline: 5.4836x; 1.4578x over previous
#include <cuda_runtime.h>
#include <cuda_fp16.h>
#include <math.h>
#include <stdint.h>

#define N_TOK 12288
#define DIMC  768
#define HEADS 12
#define HD    64
#define NWIN  192
#define BATCH 2
#define M_ROWS (BATCH * N_TOK)   // 24576
#define SHIFT 32
#define SCALE 0.125f

// ---------------- scratch (device globals) ---------------------------------
__device__ __half g_big[M_ROWS * 4 * DIMC];   // qkv scratch, later MLP hidden
__device__ __half g_hs [M_ROWS * DIMC];       // LN outputs (fp16)
__device__ __half g_o  [M_ROWS * DIMC];       // attention out (fp16)
__device__ float  g_x2 [M_ROWS * DIMC];       // x + proj residual (fp32)
#define W_QKV 0
#define W_PROJ (W_QKV + 3 * DIMC * DIMC)
#define W_FC1  (W_PROJ + DIMC * DIMC)
#define W_FC2  (W_FC1 + 4 * DIMC * DIMC)
#define W_TOT  (W_FC2 + 4 * DIMC * DIMC)
__device__ __half g_wt[W_TOT];

// ---------------- weight fp16 pre-convert ----------------------------------
__global__ __launch_bounds__(256) void cvt_kernel(
    const float4* __restrict__ in, __half* __restrict__ out, int n4)
{
    int i = blockIdx.x * 256 + threadIdx.x;
    if (i < n4) {
        float4 v = in[i];
        *(__half2*)(out + 4 * i)     = __floats2half2_rn(v.x, v.y);
        *(__half2*)(out + 4 * i + 2) = __floats2half2_rn(v.z, v.w);
    }
}

// ---------------- fused LayerNorm (+ roll), fp16 output --------------------
__global__ __launch_bounds__(256) void ln_kernel(
    const float* __restrict__ x, const float* __restrict__ g,
    const float* __restrict__ b, __half* __restrict__ out, int rollOff)
{
    int r  = blockIdx.x;
    int bb = r / N_TOK;
    int n  = r - bb * N_TOK;
    int src = bb * N_TOK + (n + rollOff) % N_TOK;
    const float* xr = x + (size_t)src * DIMC;

    int c = threadIdx.x;
    float v0 = xr[c], v1 = xr[c + 256], v2 = xr[c + 512];
    float s  = v0 + v1 + v2;
    float ss = v0 * v0 + v1 * v1 + v2 * v2;
    #pragma unroll
    for (int o = 16; o > 0; o >>= 1) {
        s  += __shfl_xor_sync(0xFFFFFFFFu, s, o);
        ss += __shfl_xor_sync(0xFFFFFFFFu, ss, o);
    }
    __shared__ float sm[8], sm2[8], stat[2];
    int warp = threadIdx.x >> 5;
    if ((threadIdx.x & 31) == 0) { sm[warp] = s; sm2[warp] = ss; }
    __syncthreads();
    if (threadIdx.x == 0) {
        float ts = 0.f, tss = 0.f;
        #pragma unroll
        for (int i = 0; i < 8; i++) { ts += sm[i]; tss += sm2[i]; }
        float m   = ts * (1.f / 768.f);
        float var = tss * (1.f / 768.f) - m * m;
        stat[0] = m;
        stat[1] = rsqrtf(var + 1e-5f);
    }
    __syncthreads();
    float m = stat[0], inv = stat[1];
    __half* orow = out + (size_t)r * DIMC;
    orow[c]       = __float2half_rn((v0 - m) * inv * g[c]       + b[c]);
    orow[c + 256] = __float2half_rn((v1 - m) * inv * g[c + 256] + b[c + 256]);
    orow[c + 512] = __float2half_rn((v2 - m) * inv * g[c + 512] + b[c + 512]);
}

// =============== fp16 mma.sync GEMM (cp.async + ldmatrix) ==================
// C = A[M,K] @ B[Nn,K]^T + bias.  A,B fp16 in gmem, fp32 accumulate.
// EPI 0: bias -> half out      1: bias+GELU -> half out
// EPI 2: bias+residual -> f32  3: bias + roll(+SHIFT) remap + residual -> f32
// 128x128x64 tile, 256 thr, warps 2(m) x 4(n), warp tile 64x32.
// SMEM: 128B rows (64 halfs), 16B chunk swizzle: phys = chunk ^ (row&7).
#define KT 64
#define STAGE_BYTES 32768     // A 16KB + B 16KB
#define NSTAGE 3
#define SMEM_GEMM (NSTAGE * STAGE_BYTES)

__device__ __forceinline__ void cp16(uint32_t dst, const void* src) {
    asm volatile("cp.async.cg.shared.global [%0], [%1], 16;\n" :: "r"(dst), "l"(src));
}
__device__ __forceinline__ void ldsm4(uint32_t& r0, uint32_t& r1,
                                      uint32_t& r2, uint32_t& r3, uint32_t a) {
    asm volatile("ldmatrix.sync.aligned.m8n8.x4.shared.b16 {%0,%1,%2,%3}, [%4];\n"
                 : "=r"(r0), "=r"(r1), "=r"(r2), "=r"(r3) : "r"(a));
}

template <int EPI>
__global__ __launch_bounds__(256, 2) void hgemm(
    const __half* __restrict__ A, const __half* __restrict__ B,
    const float* __restrict__ bias, const float* __restrict__ res,
    void* __restrict__ Cv, int M, int Nn, int K)
{
    extern __shared__ float smem[];
    uint32_t sbase = (uint32_t)__cvta_generic_to_shared(smem);

    const int tid  = threadIdx.x;
    const int lane = tid & 31;
    const int wid  = tid >> 5;
    const int wm   = wid >> 2;
    const int wn   = wid & 3;
    const int g    = lane >> 2;
    const int q    = lane & 3;

    const int rowA0 = blockIdx.y * 128;
    const int rowB0 = blockIdx.x * 128;

    // ---- cp.async coords: rows (tid>>3)+32i, 16B chunk tid&7 (8 halfs) ----
    const int ldr = tid >> 3;            // 0..31
    const int lc  = tid & 7;
    const uint32_t pcoff  = (uint32_t)((lc ^ (ldr & 7)) << 4);
    const uint32_t rowOff = (uint32_t)(ldr << 7);
    const __half* gA = A + (size_t)(rowA0 + ldr) * K + lc * 8;
    const __half* gB = B + (size_t)(rowB0 + ldr) * K + lc * 8;

    // ---- ldmatrix per-lane bases (same t8 mapping as validated tf32 ver) --
    const int t8  = lane >> 3;
    const int thA = t8 >> 1;             // k-chunk select for A
    const int tlA = t8 & 1;              // row-half select for A
    uint32_t aBaseOff[4]; int aRx[4];
    #pragma unroll
    for (int mf = 0; mf < 4; mf++) {
        int r = wm * 64 + mf * 16 + tlA * 8 + (lane & 7);
        aBaseOff[mf] = (uint32_t)(r << 7);
        aRx[mf] = r & 7;
    }
    const int tbB = t8 & 1;              // k-chunk select for B
    uint32_t bBaseOff[2]; int bRx[2];
    #pragma unroll
    for (int p = 0; p < 2; p++) {
        int n = wn * 32 + p * 16 + (t8 >> 1) * 8 + (lane & 7);
        bBaseOff[p] = (uint32_t)(n << 7);
        bRx[p] = n & 7;
    }

    float acc[4][4][4];
    #pragma unroll
    for (int a = 0; a < 4; a++)
        #pragma unroll
        for (int b = 0; b < 4; b++)
            #pragma unroll
            for (int e = 0; e < 4; e++) acc[a][b][e] = 0.f;

    const int nk = K / KT;

    auto issue = [&](int stage, int kt) {
        uint32_t sa = sbase + stage * STAGE_BYTES + rowOff + pcoff;
        uint32_t sb = sa + 16384u;
        const __half* pa = gA + kt * KT;
        const __half* pb = gB + kt * KT;
        #pragma unroll
        for (int r = 0; r < 4; r++) {
            cp16(sa + r * (32u << 7), pa + (size_t)r * 32 * K);
            cp16(sb + r * (32u << 7), pb + (size_t)r * 32 * K);
        }
        asm volatile("cp.async.commit_group;\n");
    };

    issue(0, 0);
    issue(1, 1);

    for (int kt = 0; kt < nk; kt++) {
        asm volatile("cp.async.wait_group 1;\n");
        __syncthreads();
        if (kt + 2 < nk) issue((kt + 2) % NSTAGE, kt + 2);
        else asm volatile("cp.async.commit_group;\n");

        uint32_t aS = sbase + (kt % NSTAGE) * STAGE_BYTES;
        uint32_t bS = aS + 16384u;

        #pragma unroll
        for (int j = 0; j < 4; j++) {          // k16 steps (chunks 2j, 2j+1)
            uint32_t af[4][4];
            #pragma unroll
            for (int mf = 0; mf < 4; mf++)
                ldsm4(af[mf][0], af[mf][1], af[mf][2], af[mf][3],
                      aS + aBaseOff[mf] + (uint32_t)(((2 * j + thA) ^ aRx[mf]) << 4));
            uint32_t bf[2][4];
            #pragma unroll
            for (int p = 0; p < 2; p++)
                ldsm4(bf[p][0], bf[p][1], bf[p][2], bf[p][3],
                      bS + bBaseOff[p] + (uint32_t)(((2 * j + tbB) ^ bRx[p]) << 4));
            #pragma unroll
            for (int nf = 0; nf < 4; nf++) {
                uint32_t b0 = bf[nf >> 1][(nf & 1) * 2];
                uint32_t b1 = bf[nf >> 1][(nf & 1) * 2 + 1];
                #pragma unroll
                for (int mf = 0; mf < 4; mf++) {
                    asm volatile(
                        "mma.sync.aligned.m16n8k16.row.col.f32.f16.f16.f32 "
                        "{%0,%1,%2,%3}, {%4,%5,%6,%7}, {%8,%9}, {%0,%1,%2,%3};\n"
                        : "+f"(acc[mf][nf][0]), "+f"(acc[mf][nf][1]),
                          "+f"(acc[mf][nf][2]), "+f"(acc[mf][nf][3])
                        : "r"(af[mf][0]), "r"(af[mf][1]),
                          "r"(af[mf][2]), "r"(af[mf][3]),
                          "r"(b0), "r"(b1));
                }
            }
        }
        __syncthreads();
    }

    // ---------------- epilogue ----------------
    const int r_base = blockIdx.y * 128 + wm * 64;
    const int c_base = blockIdx.x * 128 + wn * 32;
    #pragma unroll
    for (int mf = 0; mf < 4; mf++) {
        #pragma unroll
        for (int rr = 0; rr < 2; rr++) {
            int r = r_base + mf * 16 + g + rr * 8;
            int outr = r;
            if (EPI == 3) {
                int bb = r / N_TOK;
                int n  = r - bb * N_TOK;
                outr = bb * N_TOK + (n + SHIFT) % N_TOK;
            }
            const float* rrow = (EPI >= 2) ? (res + (size_t)outr * Nn) : (const float*)0;
            #pragma unroll
            for (int nf = 0; nf < 4; nf++) {
                int c = c_base + nf * 8 + q * 2;
                float2 bv = *(const float2*)&bias[c];
                float v0 = acc[mf][nf][rr * 2 + 0] + bv.x;
                float v1 = acc[mf][nf][rr * 2 + 1] + bv.y;
                if (EPI == 1) {
                    v0 = 0.5f * v0 * (1.f + erff(v0 * 0.70710678118f));
                    v1 = 0.5f * v1 * (1.f + erff(v1 * 0.70710678118f));
                }
                if (EPI >= 2) {
                    float2 rv = *(const float2*)&rrow[c];
                    v0 += rv.x; v1 += rv.y;
                    float* crow = (float*)Cv + (size_t)outr * Nn;
                    *(float2*)&crow[c] = make_float2(v0, v1);
                } else {
                    __half* crow = (__half*)Cv + (size_t)outr * Nn;
                    *(__half2*)&crow[c] = __floats2half2_rn(v0, v1);
                }
            }
        }
    }
}

// ---------------- windowed attention (fp16 in/out, fp32 compute) -----------
__device__ __forceinline__ void h8tof(const uint4& u, float* f) {
    const __half2* h = (const __half2*)&u;
    #pragma unroll
    for (int i = 0; i < 4; i++) {
        float2 t = __half22float2(h[i]);
        f[2 * i] = t.x; f[2 * i + 1] = t.y;
    }
}

__global__ __launch_bounds__(256) void attn_kernel(
    const __half* __restrict__ qkv, const float* __restrict__ table,
    __half* __restrict__ out)
{
    __shared__ float qT[64 * 64];
    __shared__ float kT[64 * 64];
    __shared__ float vs[64 * 64];

    int w = blockIdx.x, h = blockIdx.y;
    int tid = threadIdx.x;
    int i = tid >> 2;
    int c = tid & 3;
    int d0 = c * 16;

    const __half* base = qkv + (size_t)(w * 64) * (3 * DIMC) + h * HD;
    {
        const __half* qrow = base + (size_t)i * (3 * DIMC) + d0;
        const __half* krow = qrow + DIMC;
        const __half* vrow = qrow + 2 * DIMC;
        float qf[16], kf[16], vf[16];
        h8tof(*(const uint4*)qrow,       qf);
        h8tof(*(const uint4*)(qrow + 8), qf + 8);
        h8tof(*(const uint4*)krow,       kf);
        h8tof(*(const uint4*)(krow + 8), kf + 8);
        h8tof(*(const uint4*)vrow,       vf);
        h8tof(*(const uint4*)(vrow + 8), vf + 8);
        #pragma unroll
        for (int m = 0; m < 16; m++) {
            qT[(d0 + m) * 64 + i] = qf[m] * SCALE;
            kT[(d0 + m) * 64 + i] = kf[m];
            vs[i * 64 + d0 + m]   = vf[m];
        }
    }
    __syncthreads();

    float dot[16];
    #pragma unroll
    for (int m = 0; m < 16; m++) dot[m] = 0.f;
    for (int d = 0; d < 64; d++) {
        float qv = qT[d * 64 + i];
        #pragma unroll
        for (int m = 0; m < 16; m += 4) {
            float4 k4 = *(const float4*)&kT[d * 64 + d0 + m];
            dot[m + 0] += qv * k4.x;
            dot[m + 1] += qv * k4.y;
            dot[m + 2] += qv * k4.z;
            dot[m + 3] += qv * k4.w;
        }
    }

    int ri = ((i >> 1) & 1) | (((i >> 3) & 1) << 1) | (((i >> 5) & 1) << 2);
    int ci = (i & 1)        | (((i >> 2) & 1) << 1) | (((i >> 4) & 1) << 2);
    bool maskwin = (w % NWIN) == (NWIN - 1);
    #pragma unroll
    for (int m = 0; m < 16; m++) {
        int j  = d0 + m;
        int rj = ((j >> 1) & 1) | (((j >> 3) & 1) << 1) | (((j >> 5) & 1) << 2);
        int cj = (j & 1)        | (((j >> 2) & 1) << 1) | (((j >> 4) & 1) << 2);
        int rpi = (ri - rj + 7) * 15 + (ci - cj + 7);
        dot[m] += table[rpi * HEADS + h];
        if (maskwin && ((i < 32) != (j < 32))) dot[m] -= 100.f;
    }

    float mx = -1e30f;
    #pragma unroll
    for (int m = 0; m < 16; m++) mx = fmaxf(mx, dot[m]);
    mx = fmaxf(mx, __shfl_xor_sync(0xFFFFFFFFu, mx, 1));
    mx = fmaxf(mx, __shfl_xor_sync(0xFFFFFFFFu, mx, 2));
    float sum = 0.f;
    #pragma unroll
    for (int m = 0; m < 16; m++) { dot[m] = __expf(dot[m] - mx); sum += dot[m]; }
    sum += __shfl_xor_sync(0xFFFFFFFFu, sum, 1);
    sum += __shfl_xor_sync(0xFFFFFFFFu, sum, 2);
    float inv = 1.f / sum;

    __syncthreads();
    #pragma unroll
    for (int m = 0; m < 16; m++) qT[(d0 + m) * 64 + i] = dot[m] * inv;
    __syncthreads();

    float o[16];
    #pragma unroll
    for (int m = 0; m < 16; m++) o[m] = 0.f;
    for (int j = 0; j < 64; j++) {
        float a = qT[j * 64 + i];
        #pragma unroll
        for (int m = 0; m < 16; m += 4) {
            float4 v4 = *(const float4*)&vs[j * 64 + d0 + m];
            o[m + 0] += a * v4.x;
            o[m + 1] += a * v4.y;
            o[m + 2] += a * v4.z;
            o[m + 3] += a * v4.w;
        }
    }
    __half* orow = out + (size_t)(w * 64 + i) * DIMC + h * HD + d0;
    #pragma unroll
    for (int m = 0; m < 16; m += 2)
        *(__half2*)(orow + m) = __floats2half2_rn(o[m], o[m + 1]);
}

// ---------------- launch ---------------------------------------------------
extern "C" void kernel_launch(void* const* d_in, const int* in_sizes, int n_in,
                              void* d_out, int out_size)
{
    const float* x    = (const float*)d_in[0];
    const float* n1g  = (const float*)d_in[1];
    const float* n1b  = (const float*)d_in[2];
    const float* qkvw = (const float*)d_in[3];
    const float* qkvb = (const float*)d_in[4];
    const float* tab  = (const float*)d_in[5];
    const float* pw   = (const float*)d_in[6];
    const float* pb   = (const float*)d_in[7];
    const float* n2g  = (const float*)d_in[8];
    const float* n2b  = (const float*)d_in[9];
    const float* f1w  = (const float*)d_in[10];
    const float* f1b  = (const float*)d_in[11];
    const float* f2w  = (const float*)d_in[12];
    const float* f2b  = (const float*)d_in[13];
    float* out = (float*)d_out;

    __half *big, *hs, *oB, *wt;
    float *x2;
    cudaGetSymbolAddress((void**)&big, g_big);
    cudaGetSymbolAddress((void**)&hs,  g_hs);
    cudaGetSymbolAddress((void**)&oB,  g_o);
    cudaGetSymbolAddress((void**)&x2,  g_x2);
    cudaGetSymbolAddress((void**)&wt,  g_wt);
    __half* qkvB = big;
    __half* mid  = big;

    static int smem_set = 0;
    if (!smem_set) {
        cudaFuncSetAttribute(hgemm<0>, cudaFuncAttributeMaxDynamicSharedMemorySize, SMEM_GEMM);
        cudaFuncSetAttribute(hgemm<1>, cudaFuncAttributeMaxDynamicSharedMemorySize, SMEM_GEMM);
        cudaFuncSetAttribute(hgemm<2>, cudaFuncAttributeMaxDynamicSharedMemorySize, SMEM_GEMM);
        cudaFuncSetAttribute(hgemm<3>, cudaFuncAttributeMaxDynamicSharedMemorySize, SMEM_GEMM);
        smem_set = 1;
    }

    // weight fp16 pre-convert
    {
        int n;
        n = 3 * DIMC * DIMC / 4;
        cvt_kernel<<<(n + 255) / 256, 256>>>((const float4*)qkvw, wt + W_QKV, n);
        n = DIMC * DIMC / 4;
        cvt_kernel<<<(n + 255) / 256, 256>>>((const float4*)pw,   wt + W_PROJ, n);
        n = 4 * DIMC * DIMC / 4;
        cvt_kernel<<<(n + 255) / 256, 256>>>((const float4*)f1w,  wt + W_FC1, n);
        n = 4 * DIMC * DIMC / 4;
        cvt_kernel<<<(n + 255) / 256, 256>>>((const float4*)f2w,  wt + W_FC2, n);
    }

    // 1. LN1 + roll(-32)
    ln_kernel<<<M_ROWS, 256>>>(x, n1g, n1b, hs, SHIFT);
    // 2. QKV projection (24576 x 2304 x 768)
    hgemm<0><<<dim3(2304 / 128, M_ROWS / 128), 256, SMEM_GEMM>>>(
        hs, wt + W_QKV, qkvb, nullptr, qkvB, M_ROWS, 3 * DIMC, DIMC);
    // 3. windowed attention
    attn_kernel<<<dim3(BATCH * NWIN, HEADS), 256>>>(qkvB, tab, oB);
    // 4. proj + roll(+32) + residual -> x2
    hgemm<3><<<dim3(DIMC / 128, M_ROWS / 128), 256, SMEM_GEMM>>>(
        oB, wt + W_PROJ, pb, x, x2, M_ROWS, DIMC, DIMC);
    // 5. LN2
    ln_kernel<<<M_ROWS, 256>>>(x2, n2g, n2b, hs, 0);
    // 6. fc1 + GELU (24576 x 3072 x 768)
    hgemm<1><<<dim3(3072 / 128, M_ROWS / 128), 256, SMEM_GEMM>>>(
        hs, wt + W_FC1, f1b, nullptr, mid, M_ROWS, 4 * DIMC, DIMC);
    // 7. fc2 + residual -> out (24576 x 768 x 3072)
    hgemm<2><<<dim3(DIMC / 128, M_ROWS / 128), 256, SMEM_GEMM>>>(
        mid, wt + W_FC2, f2b, x2, out, M_ROWS, DIMC, 4 * DIMC);
}